// round 16
// baseline (speedup 1.0000x reference)
#include <cuda_runtime.h>
#include <cstdint>

// Problem constants (from reference)
#define L0_TOP 0.05f
#define D_CONST 0.0075f
#define DS 0.005f
#define N_STEPS 10
#define T_OUT (N_STEPS + 1)            // 11 output rows

#define TPB 64
#define WARPS (TPB / 32)
#define ROW_FLOATS (TPB * 14)          // 896 floats per block-row
#define STRIP_FLOATS (32 * 14)         // 448 floats per warp-strip
#define STRIP_BYTES  (STRIP_FLOATS * 4) // 1792 bytes

// C = A * B (3x3 row-major)
__device__ __forceinline__ void mm3(const float* __restrict__ A,
                                    const float* __restrict__ B,
                                    float* __restrict__ C) {
#pragma unroll
    for (int i = 0; i < 3; i++)
#pragma unroll
        for (int j = 0; j < 3; j++)
            C[i * 3 + j] = fmaf(A[i * 3 + 0], B[0 * 3 + j],
                           fmaf(A[i * 3 + 1], B[1 * 3 + j],
                                A[i * 3 + 2] * B[2 * 3 + j]));
}

__global__ void __launch_bounds__(TPB) sfr_rk4_tma_kernel(
    const float* __restrict__ actions,  // [B, 3]
    float* __restrict__ out,            // [11, B, 14]
    int B)
{
    // One buffer per output row (no ring, no reuse, no intra-loop waits).
    __shared__ __align__(16) float sh[T_OUT][ROW_FLOATS];

    const int tid = threadIdx.x;
    const int wid = tid >> 5;
    const int lane = tid & 31;
    const int blockStart = blockIdx.x * TPB;
    const int b = blockStart + tid;
    const bool active = (b < B);
    const int cnt = min(TPB, B - blockStart);
    const bool full = (cnt == TPB);

    float ux = 0.f, uy = 0.f;
    if (active) {
        float a1 = __ldg(actions + b * 3 + 1);
        float a2 = __ldg(actions + b * 3 + 2);
        const float ld = L0_TOP * D_CONST;   // 0.000375
        ux = a2 / (-ld);
        uy = a1 / ( ld);
    }

    // L2 policy: output lines are write-once, never read -> evict_first.
    uint64_t l2pol;
    asm("createpolicy.fractional.L2::evict_first.b64 %0, 1.0;" : "=l"(l2pol));

    const float dt = DS;

    // ---- one-time exact-RK4 linear step map: P (3x3) and q (3) ----
    // The ODE is linear with constant coefficients (ux, uy fixed per
    // trajectory): one RK4 step is exactly R <- R*P, r <- r + R*q.
    // H = dt * u_hat;  u_hat rows: (0,0,uy), (0,0,-ux), (-uy,ux,0)
    float H[9] = { 0.f,       0.f,      dt * uy,
                   0.f,       0.f,     -dt * ux,
                  -dt * uy,   dt * ux,  0.f };
    float S2[9], S3[9], S4[9], T[9], W[9], P[9];
#pragma unroll
    for (int i = 0; i < 9; i++) S2[i] = 0.5f * H[i];
    S2[0] += 1.f; S2[4] += 1.f; S2[8] += 1.f;          // S2 = I + H/2

    mm3(S2, H, T);
#pragma unroll
    for (int i = 0; i < 9; i++) S3[i] = 0.5f * T[i];
    S3[0] += 1.f; S3[4] += 1.f; S3[8] += 1.f;          // S3 = I + S2*H/2

    mm3(S3, H, T);
#pragma unroll
    for (int i = 0; i < 9; i++) S4[i] = T[i];
    S4[0] += 1.f; S4[4] += 1.f; S4[8] += 1.f;          // S4 = I + S3*H

    const float sixth = 1.0f / 6.0f;
#pragma unroll
    for (int i = 0; i < 9; i++)
        W[i] = sixth * (2.f * S2[i] + 2.f * S3[i] + S4[i]);
    W[0] += sixth; W[4] += sixth; W[8] += sixth;       // W = (I+2S2+2S3+S4)/6

    mm3(W, H, P);
    P[0] += 1.f; P[4] += 1.f; P[8] += 1.f;             // P = I + W*H

    const float q0 = dt * W[2];                         // q = dt * W[:,2]
    const float q1 = dt * W[5];
    const float q2 = dt * W[8];

    // ---- state: r (3) + R (9), y0: r=0, R=I ----
    float r0 = 0.f, r1 = 0.f, r2 = 0.f;
    float R[9] = {1.f, 0.f, 0.f,
                  0.f, 1.f, 0.f,
                  0.f, 0.f, 1.f};

#pragma unroll 1
    for (int t = 0; t < T_OUT; t++) {
        // ---- advance state (t==0 emits y0 unchanged) ----
        if (t > 0) {
            // r += R * q   (use R before update)
            r0 = fmaf(R[0], q0, fmaf(R[1], q1, fmaf(R[2], q2, r0)));
            r1 = fmaf(R[3], q0, fmaf(R[4], q1, fmaf(R[5], q2, r1)));
            r2 = fmaf(R[6], q0, fmaf(R[7], q1, fmaf(R[8], q2, r2)));
            // R = R * P
            float Rn[9];
#pragma unroll
            for (int i = 0; i < 3; i++)
#pragma unroll
                for (int j = 0; j < 3; j++)
                    Rn[i * 3 + j] = fmaf(R[i * 3 + 0], P[0 * 3 + j],
                                    fmaf(R[i * 3 + 1], P[1 * 3 + j],
                                         R[i * 3 + 2] * P[2 * 3 + j]));
#pragma unroll
            for (int i = 0; i < 9; i++) R[i] = Rn[i];
        }

        if (full) {
            // ---- stage this warp's packed 1792B strip (7x STS.64) ----
            // Strip is produced and consumed (by TMA issue) within ONE warp,
            // so only __syncwarp ordering is needed — no block barrier.
            {
                float2* s = reinterpret_cast<float2*>(
                    sh[t] + wid * STRIP_FLOATS + lane * 14);
                s[0] = make_float2(r0,   r1);
                s[1] = make_float2(r2,   R[0]);
                s[2] = make_float2(R[1], R[2]);
                s[3] = make_float2(R[3], R[4]);
                s[4] = make_float2(R[5], R[6]);
                s[5] = make_float2(R[7], R[8]);
                s[6] = make_float2(ux,   uy);
            }
            __syncwarp();
            // Make generic-proxy STS visible to the async (TMA) proxy.
            asm volatile("fence.proxy.async.shared::cta;" ::: "memory");

            // ---- per-warp bulk async store (1792B contiguous), no wait ----
            if (lane == 0) {
                const float* gdst = out + (size_t)t * (size_t)B * 14
                                        + (size_t)(blockStart + wid * 32) * 14;
                uint32_t ssrc = (uint32_t)__cvta_generic_to_shared(
                    sh[t] + wid * STRIP_FLOATS);
                asm volatile(
                    "cp.async.bulk.global.shared::cta.bulk_group.L2::cache_hint"
                    " [%0], [%1], %2, %3;\n\t"
                    "cp.async.bulk.commit_group;"
                    :: "l"(gdst), "r"(ssrc), "n"(STRIP_BYTES), "l"(l2pol)
                    : "memory");
            }
        } else {
            // Tail block (doesn't occur for B % TPB == 0): direct stores.
            if (active) {
                size_t base = (size_t)t * (size_t)B * 14 + (size_t)b * 14;
                float2* o = reinterpret_cast<float2*>(out + base);
                o[0] = make_float2(r0,   r1);
                o[1] = make_float2(r2,   R[0]);
                o[2] = make_float2(R[1], R[2]);
                o[3] = make_float2(R[3], R[4]);
                o[4] = make_float2(R[5], R[6]);
                o[5] = make_float2(R[7], R[8]);
                o[6] = make_float2(ux,   uy);
            }
        }
    }

    // Drain all outstanding bulk stores before CTA exit (smem lifetime).
    if (full && lane == 0) {
        asm volatile("cp.async.bulk.wait_group 0;" ::: "memory");
    }
}

extern "C" void kernel_launch(void* const* d_in, const int* in_sizes, int n_in,
                              void* d_out, int out_size) {
    const float* actions = (const float*)d_in[0];
    float* out = (float*)d_out;
    int B = in_sizes[0] / 3;  // actions is [B, 3]

    int blocks = (B + TPB - 1) / TPB;
    sfr_rk4_tma_kernel<<<blocks, TPB>>>(actions, out, B);
}

// round 17
// speedup vs baseline: 1.0034x; 1.0034x over previous
#include <cuda_runtime.h>
#include <cstdint>

// Problem constants (from reference)
#define L0_TOP 0.05f
#define D_CONST 0.0075f
#define DS 0.005f
#define N_STEPS 10
#define T_OUT (N_STEPS + 1)            // 11 output rows

#define TPB 64
#define WARPS (TPB / 32)
#define ROW_FLOATS (TPB * 14)          // 896 floats per block-row
#define STRIP_FLOATS (32 * 14)         // 448 floats per warp-strip
#define STRIP_BYTES  (STRIP_FLOATS * 4) // 1792 bytes

// C = A * B (3x3 row-major)
__device__ __forceinline__ void mm3(const float* __restrict__ A,
                                    const float* __restrict__ B,
                                    float* __restrict__ C) {
#pragma unroll
    for (int i = 0; i < 3; i++)
#pragma unroll
        for (int j = 0; j < 3; j++)
            C[i * 3 + j] = fmaf(A[i * 3 + 0], B[0 * 3 + j],
                           fmaf(A[i * 3 + 1], B[1 * 3 + j],
                                A[i * 3 + 2] * B[2 * 3 + j]));
}

__global__ void __launch_bounds__(TPB) sfr_rk4_tma_kernel(
    const float* __restrict__ actions,  // [B, 3]
    float* __restrict__ out,            // [11, B, 14]
    int B)
{
    // One buffer per output row (no ring, no reuse, no intra-loop waits).
    __shared__ __align__(16) float sh[T_OUT][ROW_FLOATS];

    const int tid = threadIdx.x;
    const int wid = tid >> 5;
    const int lane = tid & 31;
    const int blockStart = blockIdx.x * TPB;
    const int b = blockStart + tid;
    const bool active = (b < B);
    const int cnt = min(TPB, B - blockStart);
    const bool full = (cnt == TPB);

    float ux = 0.f, uy = 0.f;
    if (active) {
        float a1 = __ldg(actions + b * 3 + 1);
        float a2 = __ldg(actions + b * 3 + 2);
        const float ld = L0_TOP * D_CONST;   // 0.000375
        ux = a2 / (-ld);
        uy = a1 / ( ld);
    }

    // L2 policy: output lines are write-once, never read -> evict_first.
    uint64_t l2pol;
    asm("createpolicy.fractional.L2::evict_first.b64 %0, 1.0;" : "=l"(l2pol));

    const float dt = DS;

    // ---- one-time exact-RK4 linear step map: P (3x3) and q (3) ----
    // The ODE is linear with constant coefficients (ux, uy fixed per
    // trajectory): one RK4 step is exactly R <- R*P, r <- r + R*q.
    // H = dt * u_hat;  u_hat rows: (0,0,uy), (0,0,-ux), (-uy,ux,0)
    float H[9] = { 0.f,       0.f,      dt * uy,
                   0.f,       0.f,     -dt * ux,
                  -dt * uy,   dt * ux,  0.f };
    float S2[9], S3[9], S4[9], T[9], W[9], P[9];
#pragma unroll
    for (int i = 0; i < 9; i++) S2[i] = 0.5f * H[i];
    S2[0] += 1.f; S2[4] += 1.f; S2[8] += 1.f;          // S2 = I + H/2

    mm3(S2, H, T);
#pragma unroll
    for (int i = 0; i < 9; i++) S3[i] = 0.5f * T[i];
    S3[0] += 1.f; S3[4] += 1.f; S3[8] += 1.f;          // S3 = I + S2*H/2

    mm3(S3, H, T);
#pragma unroll
    for (int i = 0; i < 9; i++) S4[i] = T[i];
    S4[0] += 1.f; S4[4] += 1.f; S4[8] += 1.f;          // S4 = I + S3*H

    const float sixth = 1.0f / 6.0f;
#pragma unroll
    for (int i = 0; i < 9; i++)
        W[i] = sixth * (2.f * S2[i] + 2.f * S3[i] + S4[i]);
    W[0] += sixth; W[4] += sixth; W[8] += sixth;       // W = (I+2S2+2S3+S4)/6

    mm3(W, H, P);
    P[0] += 1.f; P[4] += 1.f; P[8] += 1.f;             // P = I + W*H

    const float q0 = dt * W[2];                         // q = dt * W[:,2]
    const float q1 = dt * W[5];
    const float q2 = dt * W[8];

    // ---- state: r (3) + R (9), y0: r=0, R=I ----
    float r0 = 0.f, r1 = 0.f, r2 = 0.f;
    float R[9] = {1.f, 0.f, 0.f,
                  0.f, 1.f, 0.f,
                  0.f, 0.f, 1.f};

#pragma unroll 1
    for (int t = 0; t < T_OUT; t++) {
        // ---- advance state (t==0 emits y0 unchanged) ----
        if (t > 0) {
            // r += R * q   (use R before update)
            r0 = fmaf(R[0], q0, fmaf(R[1], q1, fmaf(R[2], q2, r0)));
            r1 = fmaf(R[3], q0, fmaf(R[4], q1, fmaf(R[5], q2, r1)));
            r2 = fmaf(R[6], q0, fmaf(R[7], q1, fmaf(R[8], q2, r2)));
            // R = R * P
            float Rn[9];
#pragma unroll
            for (int i = 0; i < 3; i++)
#pragma unroll
                for (int j = 0; j < 3; j++)
                    Rn[i * 3 + j] = fmaf(R[i * 3 + 0], P[0 * 3 + j],
                                    fmaf(R[i * 3 + 1], P[1 * 3 + j],
                                         R[i * 3 + 2] * P[2 * 3 + j]));
#pragma unroll
            for (int i = 0; i < 9; i++) R[i] = Rn[i];
        }

        if (full) {
            // ---- stage this warp's packed 1792B strip (7x STS.64) ----
            // Strip is produced and consumed (by TMA issue) within ONE warp,
            // so only __syncwarp ordering is needed — no block barrier.
            {
                float2* s = reinterpret_cast<float2*>(
                    sh[t] + wid * STRIP_FLOATS + lane * 14);
                s[0] = make_float2(r0,   r1);
                s[1] = make_float2(r2,   R[0]);
                s[2] = make_float2(R[1], R[2]);
                s[3] = make_float2(R[3], R[4]);
                s[4] = make_float2(R[5], R[6]);
                s[5] = make_float2(R[7], R[8]);
                s[6] = make_float2(ux,   uy);
            }
            __syncwarp();
            // Make generic-proxy STS visible to the async (TMA) proxy.
            asm volatile("fence.proxy.async.shared::cta;" ::: "memory");

            // ---- per-warp bulk async store (1792B contiguous), no wait ----
            if (lane == 0) {
                const float* gdst = out + (size_t)t * (size_t)B * 14
                                        + (size_t)(blockStart + wid * 32) * 14;
                uint32_t ssrc = (uint32_t)__cvta_generic_to_shared(
                    sh[t] + wid * STRIP_FLOATS);
                asm volatile(
                    "cp.async.bulk.global.shared::cta.bulk_group.L2::cache_hint"
                    " [%0], [%1], %2, %3;\n\t"
                    "cp.async.bulk.commit_group;"
                    :: "l"(gdst), "r"(ssrc), "n"(STRIP_BYTES), "l"(l2pol)
                    : "memory");
            }
        } else {
            // Tail block (doesn't occur for B % TPB == 0): direct stores.
            if (active) {
                size_t base = (size_t)t * (size_t)B * 14 + (size_t)b * 14;
                float2* o = reinterpret_cast<float2*>(out + base);
                o[0] = make_float2(r0,   r1);
                o[1] = make_float2(r2,   R[0]);
                o[2] = make_float2(R[1], R[2]);
                o[3] = make_float2(R[3], R[4]);
                o[4] = make_float2(R[5], R[6]);
                o[5] = make_float2(R[7], R[8]);
                o[6] = make_float2(ux,   uy);
            }
        }
    }

    // Drain all outstanding bulk stores before CTA exit (smem lifetime).
    if (full && lane == 0) {
        asm volatile("cp.async.bulk.wait_group 0;" ::: "memory");
    }
}

extern "C" void kernel_launch(void* const* d_in, const int* in_sizes, int n_in,
                              void* d_out, int out_size) {
    const float* actions = (const float*)d_in[0];
    float* out = (float*)d_out;
    int B = in_sizes[0] / 3;  // actions is [B, 3]

    int blocks = (B + TPB - 1) / TPB;
    sfr_rk4_tma_kernel<<<blocks, TPB>>>(actions, out, B);
}